// round 16
// baseline (speedup 1.0000x reference)
#include <cuda_runtime.h>
#include <cstdint>

#define NMAX 100000
#define EMAX 1000000
#define CAP 96

// ---------------- scratch (no allocations allowed) ----------------
// NOTE: symbols ONLY referenced from device code, except via
// cudaGetSymbolAddress (true device address) for memset nodes.
__device__ float g_h1[NMAX * 64];    // lin1 output
__device__ float g_agg1[NMAX * 64];  // layer-1 aggregation
__device__ float g_h2[NMAX * 40];    // fused mid-MLP output
__device__ float g_agg2[NMAX * 40];  // layer-2 aggregation
__device__ int   g_deg[NMAX];
__device__ int   g_col[(size_t)NMAX * CAP];
__device__ int   g_idx32;

__device__ __forceinline__ uint32_t f2tf32(float x) {
    uint32_t r;
    asm("cvt.rna.tf32.f32 %0, %1;" : "=r"(r) : "f"(x));
    return r;
}

__device__ __forceinline__ void mma_tf32(float* d, const uint32_t* a, const uint32_t* b) {
    asm volatile(
        "mma.sync.aligned.m16n8k8.row.col.f32.tf32.tf32.f32 "
        "{%0,%1,%2,%3}, {%4,%5,%6,%7}, {%8,%9}, {%0,%1,%2,%3};"
        : "+f"(d[0]), "+f"(d[1]), "+f"(d[2]), "+f"(d[3])
        : "r"(a[0]), "r"(a[1]), "r"(a[2]), "r"(a[3]), "r"(b[0]), "r"(b[1]));
}

// ---------------- dtype probe ----------------
__global__ void detect_idx_kernel(const long long* __restrict__ idx, int E, long long N) {
    if (blockIdx.x == 0 && threadIdx.x == 0) {
        int is32 = 0;
        int nc = E < 64 ? E : 64;
        for (int i = 0; i < nc; i++) {
            long long v = idx[i];
            if (v < 0 || v >= N) { is32 = 1; break; }
        }
        g_idx32 = is32;
    }
}

__global__ void csr_fill_kernel(const long long* __restrict__ idx, int E) {
    int e = blockIdx.x * blockDim.x + threadIdx.x;
    if (e >= E) return;
    int s, d;
    if (g_idx32) {
        const int* p = (const int*)idx;
        s = p[e]; d = p[E + e];
    } else {
        s = (int)idx[e]; d = (int)idx[E + e];
    }
    int slot = atomicAdd(&g_deg[d], 1);
    if (slot < CAP) g_col[(size_t)d * CAP + slot] = s;
    // deg > CAP cannot occur for this workload (P ~ 1e-60 at E/N = 10)
}

// ---------------- gather F=64: persistent grid-stride, 16 nodes/tile ----------------
__global__ void __launch_bounds__(256) gather64_kernel(int N, int numTiles) {
    __shared__ int sDeg[16];
    __shared__ int sIdx[16][16];
    int t = threadIdx.x;
    int lane = t & 31, warp = t >> 5;
    int n2 = warp * 2 + (lane >> 4);       // local node 0..15
    int sl = lane & 15;

    for (int tile = blockIdx.x; tile < numTiles; tile += gridDim.x) {
        int nb = tile * 16;

        {   // phase 1: stage deg + indices (one latency round)
            int nl = t >> 4, slot = t & 15;
            int node = nb + nl;
            bool nv = node < N;
            if (slot == 0) {
                int d = nv ? g_deg[node] : 0;
                sDeg[nl] = d > CAP ? CAP : d;
            }
            sIdx[nl][slot] = nv ? g_col[(size_t)node * CAP + slot] : 0;
        }
        __syncthreads();

        int node = nb + n2;
        if (node < N) {
            int deg = sDeg[n2];
            const int* si = sIdx[n2];
            float4 acc = *(const float4*)&g_h1[(size_t)node * 64 + sl * 4];  // self-loop
            int d16 = deg < 16 ? deg : 16;
            int j = 0;
            for (; j + 8 <= d16; j += 8) {
                int s0 = si[j], s1 = si[j+1], s2 = si[j+2], s3 = si[j+3];
                int s4 = si[j+4], s5 = si[j+5], s6 = si[j+6], s7 = si[j+7];
                float4 v0 = *(const float4*)&g_h1[(size_t)s0 * 64 + sl * 4];
                float4 v1 = *(const float4*)&g_h1[(size_t)s1 * 64 + sl * 4];
                float4 v2 = *(const float4*)&g_h1[(size_t)s2 * 64 + sl * 4];
                float4 v3 = *(const float4*)&g_h1[(size_t)s3 * 64 + sl * 4];
                float4 v4 = *(const float4*)&g_h1[(size_t)s4 * 64 + sl * 4];
                float4 v5 = *(const float4*)&g_h1[(size_t)s5 * 64 + sl * 4];
                float4 v6 = *(const float4*)&g_h1[(size_t)s6 * 64 + sl * 4];
                float4 v7 = *(const float4*)&g_h1[(size_t)s7 * 64 + sl * 4];
                acc.x += ((v0.x + v1.x) + (v2.x + v3.x)) + ((v4.x + v5.x) + (v6.x + v7.x));
                acc.y += ((v0.y + v1.y) + (v2.y + v3.y)) + ((v4.y + v5.y) + (v6.y + v7.y));
                acc.z += ((v0.z + v1.z) + (v2.z + v3.z)) + ((v4.z + v5.z) + (v6.z + v7.z));
                acc.w += ((v0.w + v1.w) + (v2.w + v3.w)) + ((v4.w + v5.w) + (v6.w + v7.w));
            }
            for (; j + 4 <= d16; j += 4) {
                int s0 = si[j], s1 = si[j+1], s2 = si[j+2], s3 = si[j+3];
                float4 v0 = *(const float4*)&g_h1[(size_t)s0 * 64 + sl * 4];
                float4 v1 = *(const float4*)&g_h1[(size_t)s1 * 64 + sl * 4];
                float4 v2 = *(const float4*)&g_h1[(size_t)s2 * 64 + sl * 4];
                float4 v3 = *(const float4*)&g_h1[(size_t)s3 * 64 + sl * 4];
                acc.x += (v0.x + v1.x) + (v2.x + v3.x);
                acc.y += (v0.y + v1.y) + (v2.y + v3.y);
                acc.z += (v0.z + v1.z) + (v2.z + v3.z);
                acc.w += (v0.w + v1.w) + (v2.w + v3.w);
            }
            for (; j < d16; j++) {
                int s = si[j];
                float4 v = *(const float4*)&g_h1[(size_t)s * 64 + sl * 4];
                acc.x += v.x; acc.y += v.y; acc.z += v.z; acc.w += v.w;
            }
            // rare tail: deg > 16 (~3% of nodes)
            const int* cp = g_col + (size_t)node * CAP;
            for (; j < deg; j++) {
                int s = cp[j];
                float4 v = *(const float4*)&g_h1[(size_t)s * 64 + sl * 4];
                acc.x += v.x; acc.y += v.y; acc.z += v.z; acc.w += v.w;
            }
            *(float4*)&g_agg1[(size_t)node * 64 + sl * 4] = acc;
        }
        __syncthreads();   // protect sIdx/sDeg before next tile overwrites
    }
}

// ---------------- gather F=40: persistent grid-stride, 24 nodes/tile ----------------
__global__ void __launch_bounds__(256) gather40_kernel(int N, int numTiles) {
    __shared__ int sDeg[24];
    __shared__ int sIdx[24][16];
    int t = threadIdx.x;
    int lane = t & 31, warp = t >> 5;
    int sub = (lane * 13) >> 7;            // lane/10 for lane<30
    int sl  = lane - sub * 10;
    int n2 = warp * 3 + sub;               // local node 0..23

    for (int tile = blockIdx.x; tile < numTiles; tile += gridDim.x) {
        int nb = tile * 24;

        {   // phase 1
            if (t < 24) {
                int node = nb + t;
                int d = (node < N) ? g_deg[node] : 0;
                sDeg[t] = d > CAP ? CAP : d;
            }
            for (int i = t; i < 24 * 16; i += 256) {
                int nl = i >> 4, slot = i & 15;
                int node = nb + nl;
                sIdx[nl][slot] = (node < N) ? g_col[(size_t)node * CAP + slot] : 0;
            }
        }
        __syncthreads();

        int node = nb + n2;
        if (sub < 3 && node < N) {
            int deg = sDeg[n2];
            const int* si = sIdx[n2];
            float4 acc = *(const float4*)&g_h2[(size_t)node * 40 + sl * 4];  // self-loop
            int d16 = deg < 16 ? deg : 16;
            int j = 0;
            for (; j + 8 <= d16; j += 8) {
                int s0 = si[j], s1 = si[j+1], s2 = si[j+2], s3 = si[j+3];
                int s4 = si[j+4], s5 = si[j+5], s6 = si[j+6], s7 = si[j+7];
                float4 v0 = *(const float4*)&g_h2[(size_t)s0 * 40 + sl * 4];
                float4 v1 = *(const float4*)&g_h2[(size_t)s1 * 40 + sl * 4];
                float4 v2 = *(const float4*)&g_h2[(size_t)s2 * 40 + sl * 4];
                float4 v3 = *(const float4*)&g_h2[(size_t)s3 * 40 + sl * 4];
                float4 v4 = *(const float4*)&g_h2[(size_t)s4 * 40 + sl * 4];
                float4 v5 = *(const float4*)&g_h2[(size_t)s5 * 40 + sl * 4];
                float4 v6 = *(const float4*)&g_h2[(size_t)s6 * 40 + sl * 4];
                float4 v7 = *(const float4*)&g_h2[(size_t)s7 * 40 + sl * 4];
                acc.x += ((v0.x + v1.x) + (v2.x + v3.x)) + ((v4.x + v5.x) + (v6.x + v7.x));
                acc.y += ((v0.y + v1.y) + (v2.y + v3.y)) + ((v4.y + v5.y) + (v6.y + v7.y));
                acc.z += ((v0.z + v1.z) + (v2.z + v3.z)) + ((v4.z + v5.z) + (v6.z + v7.z));
                acc.w += ((v0.w + v1.w) + (v2.w + v3.w)) + ((v4.w + v5.w) + (v6.w + v7.w));
            }
            for (; j + 4 <= d16; j += 4) {
                int s0 = si[j], s1 = si[j+1], s2 = si[j+2], s3 = si[j+3];
                float4 v0 = *(const float4*)&g_h2[(size_t)s0 * 40 + sl * 4];
                float4 v1 = *(const float4*)&g_h2[(size_t)s1 * 40 + sl * 4];
                float4 v2 = *(const float4*)&g_h2[(size_t)s2 * 40 + sl * 4];
                float4 v3 = *(const float4*)&g_h2[(size_t)s3 * 40 + sl * 4];
                acc.x += (v0.x + v1.x) + (v2.x + v3.x);
                acc.y += (v0.y + v1.y) + (v2.y + v3.y);
                acc.z += (v0.z + v1.z) + (v2.z + v3.z);
                acc.w += (v0.w + v1.w) + (v2.w + v3.w);
            }
            for (; j < d16; j++) {
                int s = si[j];
                float4 v = *(const float4*)&g_h2[(size_t)s * 40 + sl * 4];
                acc.x += v.x; acc.y += v.y; acc.z += v.z; acc.w += v.w;
            }
            const int* cp = g_col + (size_t)node * CAP;
            for (; j < deg; j++) {
                int s = cp[j];
                float4 v = *(const float4*)&g_h2[(size_t)s * 40 + sl * 4];
                acc.x += v.x; acc.y += v.y; acc.z += v.z; acc.w += v.w;
            }
            *(float4*)&g_agg2[(size_t)node * 40 + sl * 4] = acc;
        }
        __syncthreads();
    }
}

// ======== tf32 fragment GEMM helpers [R15 verbatim] ========
template<int K, int NT>
__device__ __forceinline__ void stage_B(const float* __restrict__ W, uint32_t* sB, int t) {
    constexpr int KT = K / 8;
    for (int i = t; i < KT * NT * 32; i += 256) {
        int l = i & 31;
        int tile = i >> 5;
        int nt = tile % NT, kt = tile / NT;
        int f  = nt * 8 + (l >> 2);
        int k0 = kt * 8 + (l & 3);
        sB[i * 2 + 0] = f2tf32(W[f * K + k0]);
        sB[i * 2 + 1] = f2tf32(W[f * K + k0 + 4]);
    }
}

template<int KTOT, int NT>
__device__ __forceinline__ void stage_B_chunk(const float* __restrict__ W, uint32_t* sB,
                                              int t, int kbase) {
    for (int i = t; i < 8 * NT * 32; i += 256) {
        int l = i & 31;
        int tile = i >> 5;
        int nt = tile % NT, kt = tile / NT;
        int f = nt * 8 + (l >> 2);
        int k = kbase + kt * 8 + (l & 3);
        sB[i * 2 + 0] = f2tf32(W[f * KTOT + k]);
        sB[i * 2 + 1] = f2tf32(W[f * KTOT + k + 4]);
    }
}

template<int K, int NT, int PAD, bool ZERO>
__device__ __forceinline__ void mma_direct(const float* sAct, const uint32_t* sB,
                                           float acc[][4], int warp, int lane) {
    constexpr int KT = K / 8;
    int g = lane >> 2, c = lane & 3;
    const float* ap = sAct + (warp * 16 + g) * PAD + c;
    if (ZERO) {
#pragma unroll
        for (int nt = 0; nt < NT; nt++)
#pragma unroll
            for (int j = 0; j < 4; j++) acc[nt][j] = 0.f;
    }
#pragma unroll
    for (int kt = 0; kt < KT; kt++) {
        uint32_t a[4];
        a[0] = f2tf32(ap[kt * 8]);
        a[1] = f2tf32(ap[8 * PAD + kt * 8]);
        a[2] = f2tf32(ap[kt * 8 + 4]);
        a[3] = f2tf32(ap[8 * PAD + kt * 8 + 4]);
#pragma unroll
        for (int nt = 0; nt < NT; nt++) {
            uint32_t b[2];
            *(float2*)b = *(const float2*)&sB[((kt * NT + nt) * 32 + lane) * 2];
            mma_tf32(acc[nt], a, b);
        }
    }
}

template<int NT, int PAD, bool RELU>
__device__ __forceinline__ void epi_to_smem(float acc[][4], const float* __restrict__ bias,
                                            float* sAct, int warp, int lane) {
    int row = lane >> 2;
    int cb  = (lane & 3) * 2;
    int r1 = warp * 16 + row, r2 = r1 + 8;
#pragma unroll
    for (int nt = 0; nt < NT; nt++) {
        int f = nt * 8 + cb;
        float bx = __ldg(bias + f), by = __ldg(bias + f + 1);
        float2 v1 = make_float2(acc[nt][0] + bx, acc[nt][1] + by);
        float2 v2 = make_float2(acc[nt][2] + bx, acc[nt][3] + by);
        if (RELU) {
            v1.x = fmaxf(v1.x, 0.f); v1.y = fmaxf(v1.y, 0.f);
            v2.x = fmaxf(v2.x, 0.f); v2.y = fmaxf(v2.y, 0.f);
        }
        *(float2*)&sAct[r1 * PAD + f] = v1;
        *(float2*)&sAct[r2 * PAD + f] = v2;
    }
}

template<int NT, int NF, bool RELU>
__device__ __forceinline__ void epi_to_gmem(float acc[][4], const float* __restrict__ bias,
                                            float* __restrict__ Y, int n0, int N,
                                            int warp, int lane) {
    int row = lane >> 2;
    int cb  = (lane & 3) * 2;
    int gn1 = n0 + warp * 16 + row;
    int gn2 = gn1 + 8;
#pragma unroll
    for (int nt = 0; nt < NT; nt++) {
        int f = nt * 8 + cb;
        float bx = __ldg(bias + f), by = __ldg(bias + f + 1);
        float2 v1 = make_float2(acc[nt][0] + bx, acc[nt][1] + by);
        float2 v2 = make_float2(acc[nt][2] + bx, acc[nt][3] + by);
        if (RELU) {
            v1.x = fmaxf(v1.x, 0.f); v1.y = fmaxf(v1.y, 0.f);
            v2.x = fmaxf(v2.x, 0.f); v2.y = fmaxf(v2.y, 0.f);
        }
        if (gn1 < N) *(float2*)&Y[(size_t)gn1 * NF + f] = v1;
        if (gn2 < N) *(float2*)&Y[(size_t)gn2 * NF + f] = v2;
    }
}

// ---------------- lin1: g_h1 = x @ W^T + b  (128 -> 64)  [R15 verbatim] ----------------
__global__ void __launch_bounds__(256)
lin1_mma(const float* __restrict__ X, const float* __restrict__ W,
         const float* __restrict__ bias, int N)
{
    constexpr int NT = 8;
    constexpr int PAD = 68;
    extern __shared__ float sm[];
    float* sAct  = sm;                           // 128*68 f = 34816 B
    uint32_t* sB = (uint32_t*)(sm + 128 * PAD);  // 4096 u32 = 16384 B (per-chunk)

    int t = threadIdx.x, warp = t >> 5, lane = t & 31;
    int n0 = blockIdx.x * 128;

    float acc[NT][4];
#pragma unroll
    for (int nt = 0; nt < NT; nt++)
#pragma unroll
        for (int j = 0; j < 4; j++) acc[nt][j] = 0.f;

    for (int ch = 0; ch < 2; ch++) {
        if (ch) __syncthreads();
        for (int i = t; i < 128 * 16; i += 256) {
            int n = i >> 4, q = i & 15;
            int gn = n0 + n;
            float4 v = (gn < N) ? *(const float4*)&X[(size_t)gn * 128 + ch * 64 + q * 4]
                                : make_float4(0.f, 0.f, 0.f, 0.f);
            *(float4*)&sAct[n * PAD + q * 4] = v;
        }
        stage_B_chunk<128, NT>(W, sB, t, ch * 64);
        __syncthreads();
        mma_direct<64, NT, PAD, false>(sAct, sB, acc, warp, lane);
    }
    epi_to_gmem<NT, 64, false>(acc, bias, g_h1, n0, N, warp, lane);
}

// ---------------- fused mid-MLP (reads g_agg1)  [R15 verbatim] ----------------
__global__ void __launch_bounds__(256)
fused_mlp1(const float* __restrict__ W1, const float* __restrict__ b1,
           const float* __restrict__ W2, const float* __restrict__ b2,
           const float* __restrict__ W3, const float* __restrict__ b3, int N)
{
    constexpr int PAD = 68;
    extern __shared__ float sm[];
    float* sAct  = sm;
    uint32_t* sB = (uint32_t*)(sm + 128 * PAD);

    int t = threadIdx.x, warp = t >> 5, lane = t & 31;
    int n0 = blockIdx.x * 128;

    stage_B<64, 8>(W1, sB, t);
    for (int i = t; i < 128 * 16; i += 256) {
        int n = i >> 4, q = i & 15;
        int gn = n0 + n;
        float4 v = (gn < N) ? *(const float4*)&g_agg1[(size_t)gn * 64 + q * 4]
                            : make_float4(0.f, 0.f, 0.f, 0.f);
        v.x = fmaxf(v.x, 0.f); v.y = fmaxf(v.y, 0.f);
        v.z = fmaxf(v.z, 0.f); v.w = fmaxf(v.w, 0.f);
        *(float4*)&sAct[n * PAD + q * 4] = v;
    }
    __syncthreads();

    float acc[8][4];

    mma_direct<64, 8, PAD, true>(sAct, sB, acc, warp, lane);
    __syncthreads();
    epi_to_smem<8, PAD, true>(acc, b1, sAct, warp, lane);
    stage_B<64, 8>(W2, sB, t);
    __syncthreads();

    mma_direct<64, 8, PAD, true>(sAct, sB, acc, warp, lane);
    __syncthreads();
    epi_to_smem<8, PAD, true>(acc, b2, sAct, warp, lane);
    stage_B<64, 5>(W3, sB, t);
    __syncthreads();

    mma_direct<64, 5, PAD, true>(sAct, sB, acc, warp, lane);
    epi_to_gmem<5, 40, false>(acc, b3, g_h2, n0, N, warp, lane);
}

// ---------------- fused final MLP (reads g_agg2)  [R15 verbatim] ----------------
__global__ void __launch_bounds__(256)
fused_mlp2(const float* __restrict__ W1, const float* __restrict__ b1,
           const float* __restrict__ W2, const float* __restrict__ b2,
           float* __restrict__ out, int N)
{
    constexpr int PAD = 44;
    extern __shared__ float sm[];
    float* sAct   = sm;
    uint32_t* sB1 = (uint32_t*)(sm + 128 * PAD);
    uint32_t* sB2 = sB1 + 1600;

    int t = threadIdx.x, warp = t >> 5, lane = t & 31;
    int n0 = blockIdx.x * 128;

    stage_B<40, 5>(W1, sB1, t);
    stage_B<40, 5>(W2, sB2, t);

    for (int i = t; i < 128 * 10; i += 256) {
        int n = i / 10, q = i - n * 10;
        int gn = n0 + n;
        float4 v = (gn < N) ? *(const float4*)&g_agg2[(size_t)gn * 40 + q * 4]
                            : make_float4(0.f, 0.f, 0.f, 0.f);
        v.x = fmaxf(v.x, 0.f); v.y = fmaxf(v.y, 0.f);
        v.z = fmaxf(v.z, 0.f); v.w = fmaxf(v.w, 0.f);
        *(float4*)&sAct[n * PAD + q * 4] = v;
    }
    __syncthreads();

    float acc[5][4];

    mma_direct<40, 5, PAD, true>(sAct, sB1, acc, warp, lane);
    __syncthreads();
    epi_to_smem<5, PAD, true>(acc, b1, sAct, warp, lane);
    __syncthreads();

    mma_direct<40, 5, PAD, true>(sAct, sB2, acc, warp, lane);
    epi_to_gmem<5, 40, false>(acc, b2, out, n0, N, warp, lane);
}

// ---------------- launch ----------------
extern "C" void kernel_launch(void* const* d_in, const int* in_sizes, int n_in,
                              void* d_out, int out_size) {
    const float*     x   = (const float*)d_in[0];
    const long long* idx = (const long long*)d_in[1];
    const float* w1_lin = (const float*)d_in[2];
    const float* b1_lin = (const float*)d_in[3];
    const float* w1_o1  = (const float*)d_in[4];
    const float* b1_o1  = (const float*)d_in[5];
    const float* w1_o2  = (const float*)d_in[6];
    const float* b1_o2  = (const float*)d_in[7];
    const float* w2_lin = (const float*)d_in[8];
    const float* b2_lin = (const float*)d_in[9];
    const float* w2_o1  = (const float*)d_in[10];
    const float* b2_o1  = (const float*)d_in[11];
    const float* w2_o2  = (const float*)d_in[12];
    const float* b2_o2  = (const float*)d_in[13];
    float* out = (float*)d_out;

    int N = in_sizes[0] / 128;
    int E = in_sizes[1] / 2;

    const int SM_LIN1 = (128 * 68) * 4 + 4096 * 4;        // 51200 -> 4 blk/SM
    const int SM_MLP1 = (128 * 68) * 4 + 4096 * 4;        // 51200
    const int SM_MLP2 = (128 * 44) * 4 + 3200 * 4;        // 35328

    cudaFuncSetAttribute(lin1_mma,   cudaFuncAttributeMaxDynamicSharedMemorySize, SM_LIN1);
    cudaFuncSetAttribute(fused_mlp1, cudaFuncAttributeMaxDynamicSharedMemorySize, SM_MLP1);
    cudaFuncSetAttribute(fused_mlp2, cudaFuncAttributeMaxDynamicSharedMemorySize, SM_MLP2);

    static cudaStream_t s2 = nullptr;
    static cudaEvent_t evF = nullptr, evJ = nullptr;
    if (s2 == nullptr) {
        cudaStreamCreateWithFlags(&s2, cudaStreamNonBlocking);
        cudaEventCreateWithFlags(&evF, cudaEventDisableTiming);
        cudaEventCreateWithFlags(&evJ, cudaEventDisableTiming);
    }
    void* degPtr = nullptr;
    cudaGetSymbolAddress(&degPtr, g_deg);

    int gemmBlocks = (N + 127) / 128;
    const int PERSIST = 148 * 8;   // fill every SM at its 8-block warp limit

    // fork: CSR build on side stream, concurrent with lin1 on main stream
    cudaEventRecord(evF, 0);
    cudaStreamWaitEvent(s2, evF, 0);
    cudaMemsetAsync(degPtr, 0, (size_t)N * sizeof(int), s2);
    detect_idx_kernel<<<1, 32, 0, s2>>>(idx, E, (long long)N);
    csr_fill_kernel<<<(E + 255) / 256, 256, 0, s2>>>(idx, E);
    cudaEventRecord(evJ, s2);

    lin1_mma<<<gemmBlocks, 256, SM_LIN1>>>(x, w1_lin, b1_lin, N);

    cudaStreamWaitEvent(0, evJ, 0);

    // layer 1: persistent gather + fused MLP
    int tiles64 = (N + 15) / 16;
    gather64_kernel<<<(tiles64 < PERSIST ? tiles64 : PERSIST), 256>>>(N, tiles64);
    fused_mlp1<<<gemmBlocks, 256, SM_MLP1>>>(w1_o1, b1_o1, w1_o2, b1_o2,
                                             w2_lin, b2_lin, N);

    // layer 2: persistent gather + fused MLP
    int tiles40 = (N + 23) / 24;
    gather40_kernel<<<(tiles40 < PERSIST ? tiles40 : PERSIST), 256>>>(N, tiles40);
    fused_mlp2<<<gemmBlocks, 256, SM_MLP2>>>(w2_o1, b2_o1, w2_o2, b2_o2, out, N);
}

// round 17
// speedup vs baseline: 1.1311x; 1.1311x over previous
#include <cuda_runtime.h>
#include <cstdint>

#define NMAX 100000
#define EMAX 1000000
#define CAP 96

// ---------------- scratch (no allocations allowed) ----------------
// NOTE: symbols ONLY referenced from device code, except via
// cudaGetSymbolAddress (true device address) for memset nodes.
__device__ float g_h1[NMAX * 64];    // lin1 output
__device__ float g_agg1[NMAX * 64];  // layer-1 aggregation
__device__ float g_h2[NMAX * 40];    // fused mid-MLP output
__device__ float g_agg2[NMAX * 40];  // layer-2 aggregation
__device__ int   g_deg[NMAX];
__device__ int   g_col[(size_t)NMAX * CAP];
__device__ int   g_idx32;

__device__ __forceinline__ uint32_t f2tf32(float x) {
    uint32_t r;
    asm("cvt.rna.tf32.f32 %0, %1;" : "=r"(r) : "f"(x));
    return r;
}

__device__ __forceinline__ void mma_tf32(float* d, const uint32_t* a, const uint32_t* b) {
    asm volatile(
        "mma.sync.aligned.m16n8k8.row.col.f32.tf32.tf32.f32 "
        "{%0,%1,%2,%3}, {%4,%5,%6,%7}, {%8,%9}, {%0,%1,%2,%3};"
        : "+f"(d[0]), "+f"(d[1]), "+f"(d[2]), "+f"(d[3])
        : "r"(a[0]), "r"(a[1]), "r"(a[2]), "r"(a[3]), "r"(b[0]), "r"(b[1]));
}

// ---------------- dtype probe ----------------
__global__ void detect_idx_kernel(const long long* __restrict__ idx, int E, long long N) {
    if (blockIdx.x == 0 && threadIdx.x == 0) {
        int is32 = 0;
        int nc = E < 64 ? E : 64;
        for (int i = 0; i < nc; i++) {
            long long v = idx[i];
            if (v < 0 || v >= N) { is32 = 1; break; }
        }
        g_idx32 = is32;
    }
}

__global__ void csr_fill_kernel(const long long* __restrict__ idx, int E) {
    int e = blockIdx.x * blockDim.x + threadIdx.x;
    if (e >= E) return;
    int s, d;
    if (g_idx32) {
        const int* p = (const int*)idx;
        s = p[e]; d = p[E + e];
    } else {
        s = (int)idx[e]; d = (int)idx[E + e];
    }
    int slot = atomicAdd(&g_deg[d], 1);
    if (slot < CAP) g_col[(size_t)d * CAP + slot] = s;
    // deg > CAP cannot occur for this workload (P ~ 1e-60 at E/N = 10)
}

// ---------------- gather F=64: 8 nodes/block, 128 threads, smem-staged indices ----------------
__global__ void __launch_bounds__(128) gather64_kernel(int N) {
    __shared__ int sDeg[8];
    __shared__ int sIdx[8][16];
    int t = threadIdx.x;
    int nb = blockIdx.x * 8;

    {   // phase 1: stage deg + indices (one latency round, all independent)
        int nl = t >> 4, slot = t & 15;
        int node = nb + nl;
        bool nv = node < N;
        if (slot == 0) {
            int d = nv ? g_deg[node] : 0;
            sDeg[nl] = d > CAP ? CAP : d;
        }
        sIdx[nl][slot] = nv ? g_col[(size_t)node * CAP + slot] : 0;
    }
    __syncthreads();

    int lane = t & 31, warp = t >> 5;
    int n2 = warp * 2 + (lane >> 4);       // local node 0..7
    int sl = lane & 15;
    int node = nb + n2;
    if (node >= N) return;

    int deg = sDeg[n2];
    const int* si = sIdx[n2];
    float4 acc = *(const float4*)&g_h1[(size_t)node * 64 + sl * 4];  // self-loop
    int d16 = deg < 16 ? deg : 16;
    int j = 0;
    for (; j + 8 <= d16; j += 8) {
        int s0 = si[j], s1 = si[j+1], s2 = si[j+2], s3 = si[j+3];
        int s4 = si[j+4], s5 = si[j+5], s6 = si[j+6], s7 = si[j+7];
        float4 v0 = *(const float4*)&g_h1[(size_t)s0 * 64 + sl * 4];
        float4 v1 = *(const float4*)&g_h1[(size_t)s1 * 64 + sl * 4];
        float4 v2 = *(const float4*)&g_h1[(size_t)s2 * 64 + sl * 4];
        float4 v3 = *(const float4*)&g_h1[(size_t)s3 * 64 + sl * 4];
        float4 v4 = *(const float4*)&g_h1[(size_t)s4 * 64 + sl * 4];
        float4 v5 = *(const float4*)&g_h1[(size_t)s5 * 64 + sl * 4];
        float4 v6 = *(const float4*)&g_h1[(size_t)s6 * 64 + sl * 4];
        float4 v7 = *(const float4*)&g_h1[(size_t)s7 * 64 + sl * 4];
        acc.x += ((v0.x + v1.x) + (v2.x + v3.x)) + ((v4.x + v5.x) + (v6.x + v7.x));
        acc.y += ((v0.y + v1.y) + (v2.y + v3.y)) + ((v4.y + v5.y) + (v6.y + v7.y));
        acc.z += ((v0.z + v1.z) + (v2.z + v3.z)) + ((v4.z + v5.z) + (v6.z + v7.z));
        acc.w += ((v0.w + v1.w) + (v2.w + v3.w)) + ((v4.w + v5.w) + (v6.w + v7.w));
    }
    for (; j + 4 <= d16; j += 4) {
        int s0 = si[j], s1 = si[j+1], s2 = si[j+2], s3 = si[j+3];
        float4 v0 = *(const float4*)&g_h1[(size_t)s0 * 64 + sl * 4];
        float4 v1 = *(const float4*)&g_h1[(size_t)s1 * 64 + sl * 4];
        float4 v2 = *(const float4*)&g_h1[(size_t)s2 * 64 + sl * 4];
        float4 v3 = *(const float4*)&g_h1[(size_t)s3 * 64 + sl * 4];
        acc.x += (v0.x + v1.x) + (v2.x + v3.x);
        acc.y += (v0.y + v1.y) + (v2.y + v3.y);
        acc.z += (v0.z + v1.z) + (v2.z + v3.z);
        acc.w += (v0.w + v1.w) + (v2.w + v3.w);
    }
    for (; j < d16; j++) {
        int s = si[j];
        float4 v = *(const float4*)&g_h1[(size_t)s * 64 + sl * 4];
        acc.x += v.x; acc.y += v.y; acc.z += v.z; acc.w += v.w;
    }
    // rare tail: deg > 16 (~3% of nodes)
    const int* cp = g_col + (size_t)node * CAP;
    for (; j < deg; j++) {
        int s = cp[j];
        float4 v = *(const float4*)&g_h1[(size_t)s * 64 + sl * 4];
        acc.x += v.x; acc.y += v.y; acc.z += v.z; acc.w += v.w;
    }
    *(float4*)&g_agg1[(size_t)node * 64 + sl * 4] = acc;
}

// ---------------- gather F=40: 12 nodes/block, 128 threads, smem-staged indices ----------------
__global__ void __launch_bounds__(128) gather40_kernel(int N) {
    __shared__ int sDeg[12];
    __shared__ int sIdx[12][16];
    int t = threadIdx.x;
    int nb = blockIdx.x * 12;

    {   // phase 1
        if (t < 12) {
            int node = nb + t;
            int d = (node < N) ? g_deg[node] : 0;
            sDeg[t] = d > CAP ? CAP : d;
        }
        for (int i = t; i < 12 * 16; i += 128) {
            int nl = i >> 4, slot = i & 15;
            int node = nb + nl;
            sIdx[nl][slot] = (node < N) ? g_col[(size_t)node * CAP + slot] : 0;
        }
    }
    __syncthreads();

    int lane = t & 31, warp = t >> 5;
    int sub = (lane * 13) >> 7;            // lane/10 for lane<30
    int sl  = lane - sub * 10;
    if (sub >= 3) return;
    int n2 = warp * 3 + sub;               // local node 0..11
    int node = nb + n2;
    if (node >= N) return;

    int deg = sDeg[n2];
    const int* si = sIdx[n2];
    float4 acc = *(const float4*)&g_h2[(size_t)node * 40 + sl * 4];  // self-loop
    int d16 = deg < 16 ? deg : 16;
    int j = 0;
    for (; j + 8 <= d16; j += 8) {
        int s0 = si[j], s1 = si[j+1], s2 = si[j+2], s3 = si[j+3];
        int s4 = si[j+4], s5 = si[j+5], s6 = si[j+6], s7 = si[j+7];
        float4 v0 = *(const float4*)&g_h2[(size_t)s0 * 40 + sl * 4];
        float4 v1 = *(const float4*)&g_h2[(size_t)s1 * 40 + sl * 4];
        float4 v2 = *(const float4*)&g_h2[(size_t)s2 * 40 + sl * 4];
        float4 v3 = *(const float4*)&g_h2[(size_t)s3 * 40 + sl * 4];
        float4 v4 = *(const float4*)&g_h2[(size_t)s4 * 40 + sl * 4];
        float4 v5 = *(const float4*)&g_h2[(size_t)s5 * 40 + sl * 4];
        float4 v6 = *(const float4*)&g_h2[(size_t)s6 * 40 + sl * 4];
        float4 v7 = *(const float4*)&g_h2[(size_t)s7 * 40 + sl * 4];
        acc.x += ((v0.x + v1.x) + (v2.x + v3.x)) + ((v4.x + v5.x) + (v6.x + v7.x));
        acc.y += ((v0.y + v1.y) + (v2.y + v3.y)) + ((v4.y + v5.y) + (v6.y + v7.y));
        acc.z += ((v0.z + v1.z) + (v2.z + v3.z)) + ((v4.z + v5.z) + (v6.z + v7.z));
        acc.w += ((v0.w + v1.w) + (v2.w + v3.w)) + ((v4.w + v5.w) + (v6.w + v7.w));
    }
    for (; j + 4 <= d16; j += 4) {
        int s0 = si[j], s1 = si[j+1], s2 = si[j+2], s3 = si[j+3];
        float4 v0 = *(const float4*)&g_h2[(size_t)s0 * 40 + sl * 4];
        float4 v1 = *(const float4*)&g_h2[(size_t)s1 * 40 + sl * 4];
        float4 v2 = *(const float4*)&g_h2[(size_t)s2 * 40 + sl * 4];
        float4 v3 = *(const float4*)&g_h2[(size_t)s3 * 40 + sl * 4];
        acc.x += (v0.x + v1.x) + (v2.x + v3.x);
        acc.y += (v0.y + v1.y) + (v2.y + v3.y);
        acc.z += (v0.z + v1.z) + (v2.z + v3.z);
        acc.w += (v0.w + v1.w) + (v2.w + v3.w);
    }
    for (; j < d16; j++) {
        int s = si[j];
        float4 v = *(const float4*)&g_h2[(size_t)s * 40 + sl * 4];
        acc.x += v.x; acc.y += v.y; acc.z += v.z; acc.w += v.w;
    }
    const int* cp = g_col + (size_t)node * CAP;
    for (; j < deg; j++) {
        int s = cp[j];
        float4 v = *(const float4*)&g_h2[(size_t)s * 40 + sl * 4];
        acc.x += v.x; acc.y += v.y; acc.z += v.z; acc.w += v.w;
    }
    *(float4*)&g_agg2[(size_t)node * 40 + sl * 4] = acc;
}

// ======== tf32 fragment GEMM helpers [R15 verbatim] ========
template<int K, int NT>
__device__ __forceinline__ void stage_B(const float* __restrict__ W, uint32_t* sB, int t) {
    constexpr int KT = K / 8;
    for (int i = t; i < KT * NT * 32; i += 256) {
        int l = i & 31;
        int tile = i >> 5;
        int nt = tile % NT, kt = tile / NT;
        int f  = nt * 8 + (l >> 2);
        int k0 = kt * 8 + (l & 3);
        sB[i * 2 + 0] = f2tf32(W[f * K + k0]);
        sB[i * 2 + 1] = f2tf32(W[f * K + k0 + 4]);
    }
}

template<int KTOT, int NT>
__device__ __forceinline__ void stage_B_chunk(const float* __restrict__ W, uint32_t* sB,
                                              int t, int kbase) {
    for (int i = t; i < 8 * NT * 32; i += 256) {
        int l = i & 31;
        int tile = i >> 5;
        int nt = tile % NT, kt = tile / NT;
        int f = nt * 8 + (l >> 2);
        int k = kbase + kt * 8 + (l & 3);
        sB[i * 2 + 0] = f2tf32(W[f * KTOT + k]);
        sB[i * 2 + 1] = f2tf32(W[f * KTOT + k + 4]);
    }
}

template<int K, int NT, int PAD, bool ZERO>
__device__ __forceinline__ void mma_direct(const float* sAct, const uint32_t* sB,
                                           float acc[][4], int warp, int lane) {
    constexpr int KT = K / 8;
    int g = lane >> 2, c = lane & 3;
    const float* ap = sAct + (warp * 16 + g) * PAD + c;
    if (ZERO) {
#pragma unroll
        for (int nt = 0; nt < NT; nt++)
#pragma unroll
            for (int j = 0; j < 4; j++) acc[nt][j] = 0.f;
    }
#pragma unroll
    for (int kt = 0; kt < KT; kt++) {
        uint32_t a[4];
        a[0] = f2tf32(ap[kt * 8]);
        a[1] = f2tf32(ap[8 * PAD + kt * 8]);
        a[2] = f2tf32(ap[kt * 8 + 4]);
        a[3] = f2tf32(ap[8 * PAD + kt * 8 + 4]);
#pragma unroll
        for (int nt = 0; nt < NT; nt++) {
            uint32_t b[2];
            *(float2*)b = *(const float2*)&sB[((kt * NT + nt) * 32 + lane) * 2];
            mma_tf32(acc[nt], a, b);
        }
    }
}

template<int NT, int PAD, bool RELU>
__device__ __forceinline__ void epi_to_smem(float acc[][4], const float* __restrict__ bias,
                                            float* sAct, int warp, int lane) {
    int row = lane >> 2;
    int cb  = (lane & 3) * 2;
    int r1 = warp * 16 + row, r2 = r1 + 8;
#pragma unroll
    for (int nt = 0; nt < NT; nt++) {
        int f = nt * 8 + cb;
        float bx = __ldg(bias + f), by = __ldg(bias + f + 1);
        float2 v1 = make_float2(acc[nt][0] + bx, acc[nt][1] + by);
        float2 v2 = make_float2(acc[nt][2] + bx, acc[nt][3] + by);
        if (RELU) {
            v1.x = fmaxf(v1.x, 0.f); v1.y = fmaxf(v1.y, 0.f);
            v2.x = fmaxf(v2.x, 0.f); v2.y = fmaxf(v2.y, 0.f);
        }
        *(float2*)&sAct[r1 * PAD + f] = v1;
        *(float2*)&sAct[r2 * PAD + f] = v2;
    }
}

template<int NT, int NF, bool RELU>
__device__ __forceinline__ void epi_to_gmem(float acc[][4], const float* __restrict__ bias,
                                            float* __restrict__ Y, int n0, int N,
                                            int warp, int lane) {
    int row = lane >> 2;
    int cb  = (lane & 3) * 2;
    int gn1 = n0 + warp * 16 + row;
    int gn2 = gn1 + 8;
#pragma unroll
    for (int nt = 0; nt < NT; nt++) {
        int f = nt * 8 + cb;
        float bx = __ldg(bias + f), by = __ldg(bias + f + 1);
        float2 v1 = make_float2(acc[nt][0] + bx, acc[nt][1] + by);
        float2 v2 = make_float2(acc[nt][2] + bx, acc[nt][3] + by);
        if (RELU) {
            v1.x = fmaxf(v1.x, 0.f); v1.y = fmaxf(v1.y, 0.f);
            v2.x = fmaxf(v2.x, 0.f); v2.y = fmaxf(v2.y, 0.f);
        }
        if (gn1 < N) *(float2*)&Y[(size_t)gn1 * NF + f] = v1;
        if (gn2 < N) *(float2*)&Y[(size_t)gn2 * NF + f] = v2;
    }
}

// ---------------- lin1: g_h1 = x @ W^T + b  (128 -> 64)  [R15 verbatim] ----------------
__global__ void __launch_bounds__(256)
lin1_mma(const float* __restrict__ X, const float* __restrict__ W,
         const float* __restrict__ bias, int N)
{
    constexpr int NT = 8;
    constexpr int PAD = 68;
    extern __shared__ float sm[];
    float* sAct  = sm;                           // 128*68 f = 34816 B
    uint32_t* sB = (uint32_t*)(sm + 128 * PAD);  // 4096 u32 = 16384 B (per-chunk)

    int t = threadIdx.x, warp = t >> 5, lane = t & 31;
    int n0 = blockIdx.x * 128;

    float acc[NT][4];
#pragma unroll
    for (int nt = 0; nt < NT; nt++)
#pragma unroll
        for (int j = 0; j < 4; j++) acc[nt][j] = 0.f;

    for (int ch = 0; ch < 2; ch++) {
        if (ch) __syncthreads();
        for (int i = t; i < 128 * 16; i += 256) {
            int n = i >> 4, q = i & 15;
            int gn = n0 + n;
            float4 v = (gn < N) ? *(const float4*)&X[(size_t)gn * 128 + ch * 64 + q * 4]
                                : make_float4(0.f, 0.f, 0.f, 0.f);
            *(float4*)&sAct[n * PAD + q * 4] = v;
        }
        stage_B_chunk<128, NT>(W, sB, t, ch * 64);
        __syncthreads();
        mma_direct<64, NT, PAD, false>(sAct, sB, acc, warp, lane);
    }
    epi_to_gmem<NT, 64, false>(acc, bias, g_h1, n0, N, warp, lane);
}

// ---------------- fused mid-MLP (reads g_agg1)  [R15 verbatim] ----------------
__global__ void __launch_bounds__(256)
fused_mlp1(const float* __restrict__ W1, const float* __restrict__ b1,
           const float* __restrict__ W2, const float* __restrict__ b2,
           const float* __restrict__ W3, const float* __restrict__ b3, int N)
{
    constexpr int PAD = 68;
    extern __shared__ float sm[];
    float* sAct  = sm;
    uint32_t* sB = (uint32_t*)(sm + 128 * PAD);

    int t = threadIdx.x, warp = t >> 5, lane = t & 31;
    int n0 = blockIdx.x * 128;

    stage_B<64, 8>(W1, sB, t);
    for (int i = t; i < 128 * 16; i += 256) {
        int n = i >> 4, q = i & 15;
        int gn = n0 + n;
        float4 v = (gn < N) ? *(const float4*)&g_agg1[(size_t)gn * 64 + q * 4]
                            : make_float4(0.f, 0.f, 0.f, 0.f);
        v.x = fmaxf(v.x, 0.f); v.y = fmaxf(v.y, 0.f);
        v.z = fmaxf(v.z, 0.f); v.w = fmaxf(v.w, 0.f);
        *(float4*)&sAct[n * PAD + q * 4] = v;
    }
    __syncthreads();

    float acc[8][4];

    mma_direct<64, 8, PAD, true>(sAct, sB, acc, warp, lane);
    __syncthreads();
    epi_to_smem<8, PAD, true>(acc, b1, sAct, warp, lane);
    stage_B<64, 8>(W2, sB, t);
    __syncthreads();

    mma_direct<64, 8, PAD, true>(sAct, sB, acc, warp, lane);
    __syncthreads();
    epi_to_smem<8, PAD, true>(acc, b2, sAct, warp, lane);
    stage_B<64, 5>(W3, sB, t);
    __syncthreads();

    mma_direct<64, 5, PAD, true>(sAct, sB, acc, warp, lane);
    epi_to_gmem<5, 40, false>(acc, b3, g_h2, n0, N, warp, lane);
}

// ---------------- fused final MLP (reads g_agg2)  [R15 verbatim] ----------------
__global__ void __launch_bounds__(256)
fused_mlp2(const float* __restrict__ W1, const float* __restrict__ b1,
           const float* __restrict__ W2, const float* __restrict__ b2,
           float* __restrict__ out, int N)
{
    constexpr int PAD = 44;
    extern __shared__ float sm[];
    float* sAct   = sm;
    uint32_t* sB1 = (uint32_t*)(sm + 128 * PAD);
    uint32_t* sB2 = sB1 + 1600;

    int t = threadIdx.x, warp = t >> 5, lane = t & 31;
    int n0 = blockIdx.x * 128;

    stage_B<40, 5>(W1, sB1, t);
    stage_B<40, 5>(W2, sB2, t);

    for (int i = t; i < 128 * 10; i += 256) {
        int n = i / 10, q = i - n * 10;
        int gn = n0 + n;
        float4 v = (gn < N) ? *(const float4*)&g_agg2[(size_t)gn * 40 + q * 4]
                            : make_float4(0.f, 0.f, 0.f, 0.f);
        v.x = fmaxf(v.x, 0.f); v.y = fmaxf(v.y, 0.f);
        v.z = fmaxf(v.z, 0.f); v.w = fmaxf(v.w, 0.f);
        *(float4*)&sAct[n * PAD + q * 4] = v;
    }
    __syncthreads();

    float acc[5][4];

    mma_direct<40, 5, PAD, true>(sAct, sB1, acc, warp, lane);
    __syncthreads();
    epi_to_smem<5, PAD, true>(acc, b1, sAct, warp, lane);
    __syncthreads();

    mma_direct<40, 5, PAD, true>(sAct, sB2, acc, warp, lane);
    epi_to_gmem<5, 40, false>(acc, b2, out, n0, N, warp, lane);
}

// ---------------- launch ----------------
extern "C" void kernel_launch(void* const* d_in, const int* in_sizes, int n_in,
                              void* d_out, int out_size) {
    const float*     x   = (const float*)d_in[0];
    const long long* idx = (const long long*)d_in[1];
    const float* w1_lin = (const float*)d_in[2];
    const float* b1_lin = (const float*)d_in[3];
    const float* w1_o1  = (const float*)d_in[4];
    const float* b1_o1  = (const float*)d_in[5];
    const float* w1_o2  = (const float*)d_in[6];
    const float* b1_o2  = (const float*)d_in[7];
    const float* w2_lin = (const float*)d_in[8];
    const float* b2_lin = (const float*)d_in[9];
    const float* w2_o1  = (const float*)d_in[10];
    const float* b2_o1  = (const float*)d_in[11];
    const float* w2_o2  = (const float*)d_in[12];
    const float* b2_o2  = (const float*)d_in[13];
    float* out = (float*)d_out;

    int N = in_sizes[0] / 128;
    int E = in_sizes[1] / 2;

    const int SM_LIN1 = (128 * 68) * 4 + 4096 * 4;        // 51200 -> 4 blk/SM
    const int SM_MLP1 = (128 * 68) * 4 + 4096 * 4;        // 51200
    const int SM_MLP2 = (128 * 44) * 4 + 3200 * 4;        // 35328

    cudaFuncSetAttribute(lin1_mma,   cudaFuncAttributeMaxDynamicSharedMemorySize, SM_LIN1);
    cudaFuncSetAttribute(fused_mlp1, cudaFuncAttributeMaxDynamicSharedMemorySize, SM_MLP1);
    cudaFuncSetAttribute(fused_mlp2, cudaFuncAttributeMaxDynamicSharedMemorySize, SM_MLP2);

    static cudaStream_t s2 = nullptr;
    static cudaEvent_t evF = nullptr, evJ = nullptr;
    if (s2 == nullptr) {
        cudaStreamCreateWithFlags(&s2, cudaStreamNonBlocking);
        cudaEventCreateWithFlags(&evF, cudaEventDisableTiming);
        cudaEventCreateWithFlags(&evJ, cudaEventDisableTiming);
    }
    void* degPtr = nullptr;
    cudaGetSymbolAddress(&degPtr, g_deg);

    int gemmBlocks = (N + 127) / 128;

    // fork: CSR build on side stream, concurrent with lin1 on main stream
    cudaEventRecord(evF, 0);
    cudaStreamWaitEvent(s2, evF, 0);
    cudaMemsetAsync(degPtr, 0, (size_t)N * sizeof(int), s2);
    detect_idx_kernel<<<1, 32, 0, s2>>>(idx, E, (long long)N);
    csr_fill_kernel<<<(E + 255) / 256, 256, 0, s2>>>(idx, E);
    cudaEventRecord(evJ, s2);

    lin1_mma<<<gemmBlocks, 256, SM_LIN1>>>(x, w1_lin, b1_lin, N);

    cudaStreamWaitEvent(0, evJ, 0);

    // layer 1: standalone gather (128-thread blocks) + fused MLP
    gather64_kernel<<<(N + 7) / 8, 128>>>(N);
    fused_mlp1<<<gemmBlocks, 256, SM_MLP1>>>(w1_o1, b1_o1, w1_o2, b1_o2,
                                             w2_lin, b2_lin, N);

    // layer 2: standalone gather (128-thread blocks) + fused MLP
    gather40_kernel<<<(N + 11) / 12, 128>>>(N);
    fused_mlp2<<<gemmBlocks, 256, SM_MLP2>>>(w2_o1, b2_o1, w2_o2, b2_o2, out, N);
}